// round 13
// baseline (speedup 1.0000x reference)
#include <cuda_runtime.h>
#include <cuda_fp16.h>
#include <math.h>
#include <stdint.h>

// ---------------- problem constants ----------------
#define BB    4
#define TT    1000000
#define EE    8
#define CC    128
#define TOUT  1953
#define MROWS (BB * TOUT)          // 7812
#define MP    7936                 // padded M = 62*128
#define NCOLS 512
#define KDIM  4096
#define GCHUNKS 63                 // 31-row chunks per batch (63*31 = 1953)

// ---------------- GEMM tiling ----------------
#define BM 128
#define BN 256
#define BKC 64                     // K elems per stage
#define NKC (KDIM / BKC)           // 64 chunks
// SMEM layout (bytes, within dynamic smem):
//   A32[2] : 128 rows x 272B (16B-padded)  = 34816 each
//   A16[2] : 128 rows x 128B swizzled      = 16384 each
//   B16[3] : 256 rows x 128B swizzled      = 32768 each
#define A32_STRIDE 272
#define A32_BYTES  (128 * A32_STRIDE)      // 34816
#define OFF_A32_0  0
#define OFF_A32_1  (OFF_A32_0 + A32_BYTES)
#define OFF_A16_0  (OFF_A32_1 + A32_BYTES) // 69632
#define OFF_A16_1  (OFF_A16_0 + 16384)     // 86016
#define OFF_B_0    (OFF_A16_1 + 16384)     // 102400
#define OFF_B_1    (OFF_B_0 + 32768)
#define OFF_B_2    (OFF_B_1 + 32768)
#define SMEM_DYN   (OFF_B_2 + 32768)       // 200704

// ---------------- scratch ----------------
__device__ __half d_Bh[(size_t)NCOLS * KDIM];   // column-interleaved (a,gate pairs)
__device__ float d_U[(size_t)MP * 256];   // GLU out [row][ctx 0..127 | main 0..127]
__device__ float d_WsT[2][CC * CC];
__device__ float d_gpart[BB * GCHUNKS * CC];
__device__ float d_q[BB * CC];
__device__ float d_part[BB * GCHUNKS * CC];

// ---------------- PTX helpers ----------------
__device__ __forceinline__ uint32_t smem_u32(const void* p) {
    uint32_t a;
    asm("{ .reg .u64 t; cvta.to.shared.u64 t, %1; cvt.u32.u64 %0, t; }" : "=r"(a) : "l"(p));
    return a;
}
#define CP16(dst, src) asm volatile("cp.async.cg.shared.global [%0], [%1], 16;" :: "r"(dst), "l"(src) : "memory")
#define CP_COMMIT()    asm volatile("cp.async.commit_group;" ::: "memory")
#define CP_WAIT1()     asm volatile("cp.async.wait_group 1;" ::: "memory")

#define LDSM4(r0, r1, r2, r3, addr)                                         \
    asm volatile("ldmatrix.sync.aligned.m8n8.x4.shared.b16 {%0,%1,%2,%3}, [%4];" \
        : "=r"(r0), "=r"(r1), "=r"(r2), "=r"(r3) : "r"(addr))

#define MMA16816(d, a, b)                                                   \
    asm volatile("mma.sync.aligned.m16n8k16.row.col.f32.f16.f16.f32 "       \
        "{%0,%1,%2,%3}, {%4,%5,%6,%7}, {%8,%9}, {%0,%1,%2,%3};"             \
        : "+f"((d)[0]), "+f"((d)[1]), "+f"((d)[2]), "+f"((d)[3])            \
        : "r"((a)[0]), "r"((a)[1]), "r"((a)[2]), "r"((a)[3]),               \
          "r"((b)[0]), "r"((b)[1]))

// swizzled byte offset within a 128B-row fp16 tile: row r, 16B-column c16
__device__ __forceinline__ uint32_t tile_off(int r, int c16) {
    return (uint32_t)(r * 128 + ((c16 * 16) ^ ((r & 7) << 4)));
}

// ============================================================
// Prep: B weights -> fp16 column-interleaved; share weights -> WsT.
// blocks [0, 8192): B.  blocks [8192, 8256): WsT.
// ============================================================
__global__ void prep_w(const float* __restrict__ cw, const float* __restrict__ mw,
                       const float* __restrict__ cs, const float* __restrict__ ms) {
    int bid = blockIdx.x;
    if (bid < 8192) {
        int idx = bid * 256 + threadIdx.x;        // < NCOLS*KDIM = 2M
        int n = idx >> 12, kk = idx & 4095;
        int branch = n >> 8;
        int within = n & 255;
        int pair = within >> 1, half = within & 1;
        int oc = half * 128 + pair;               // original out-channel within branch
        int e = kk & 7, k = kk >> 3;
        const float* w = branch ? mw : cw;
        d_Bh[idx] = __float2half_rn(w[(size_t)oc * KDIM + e * 512 + k]);
    } else {
        int idx = (bid - 8192) * 256 + threadIdx.x;
        if (idx < CC * CC) {
            int o = idx / CC, c = idx % CC;
            d_WsT[0][c * CC + o] = cs[o * CC + c];
            d_WsT[1][c * CC + o] = ms[o * CC + c];
        }
    }
}

// ============================================================
// K1: fused fp32->fp16 convert + HMMA GEMM + bias/GLU -> d_U
//     grid (2, 62); 256 threads = 8 warps (2m x 4n), warp tile
//     64x64.  A read straight from x (fp32, cp.async, 2-stage),
//     converted in-SMEM to swizzled fp16; B 3-stage fp16.
// ============================================================
__global__ __launch_bounds__(256, 1) void gemm_tc(const float* __restrict__ ccb,
                                                  const float* __restrict__ mcb,
                                                  const float* __restrict__ x) {
    extern __shared__ char smem[];
    uint32_t sb = smem_u32(smem);
    int tid = threadIdx.x;
    int lane = tid & 31, wid = tid >> 5;
    int wm = wid & 1, wn = wid >> 1;          // 2 x 4 warp grid (64x64 tiles)
    int bn = blockIdx.x, bm = blockIdx.y;
    int m0 = bm * BM, n0 = bn * BN;

    const uint32_t A32o[2] = {sb + OFF_A32_0, sb + OFF_A32_1};
    const uint32_t A16o[2] = {sb + OFF_A16_0, sb + OFF_A16_1};
    const uint32_t Bo[3]   = {sb + OFF_B_0, sb + OFF_B_1, sb + OFF_B_2};

    // ---- A (fp32 from x) load mapping: rows (tid>>4)+16i, col (tid&15)*16B
    int ac16 = tid & 15;
    const float* asrc[8];
    uint32_t adst[8];
#pragma unroll
    for (int i = 0; i < 8; i++) {
        int r = (tid >> 4) + 16 * i;
        int grow = m0 + r;
        if (grow >= MROWS) grow = MROWS - 1;      // clamp pad rows (zeroed at convert)
        int b = grow / TOUT, t = grow % TOUT;
        asrc[i] = x + (size_t)b * TT * EE + (size_t)t * KDIM + ac16 * 4;
        adst[i] = (uint32_t)(r * A32_STRIDE + ac16 * 16);
    }
    // ---- B (fp16) load mapping: rows (tid>>3)+32i, col (tid&7)*16B
    int bc16 = tid & 7;
    const __half* bsrc[8];
    uint32_t bdst[8];
#pragma unroll
    for (int i = 0; i < 8; i++) {
        int r = (tid >> 3) + 32 * i;
        bsrc[i] = d_Bh + (size_t)(n0 + r) * KDIM + bc16 * 8;
        bdst[i] = tile_off(r, bc16);
    }

    // ---- ldmatrix constants
    int l15 = lane & 15, hh = lane >> 4;
    uint32_t cA[4], swA[4], cB[4], swB[4];
#pragma unroll
    for (int mt = 0; mt < 4; mt++) {
        int r = wm * 64 + mt * 16 + l15;
        cA[mt] = (uint32_t)(r * 128);
        swA[mt] = (uint32_t)((r & 7) << 4);
    }
#pragma unroll
    for (int q = 0; q < 4; q++) {
        int r = wn * 64 + q * 16 + l15;
        cB[q] = (uint32_t)(r * 128);
        swB[q] = (uint32_t)((r & 7) << 4);
    }

    // ---- convert mapping: row tid>>1, half tid&1 (32 floats each)
    int vrow = tid >> 1, vhalf = tid & 1;
    bool vpad = (m0 + vrow) >= MROWS;
    uint32_t vsrc = (uint32_t)(vrow * A32_STRIDE + vhalf * 128);
    uint32_t vdst[4];
#pragma unroll
    for (int q = 0; q < 4; q++) vdst[q] = tile_off(vrow, vhalf * 4 + q);

    float acc[4][8][4];
#pragma unroll
    for (int mt = 0; mt < 4; mt++)
#pragma unroll
        for (int nt = 0; nt < 8; nt++)
#pragma unroll
            for (int i = 0; i < 4; i++) acc[mt][nt][i] = 0.f;

    // ---- prologue: issue chunks 0, 1 ----
#pragma unroll
    for (int s = 0; s < 2; s++) {
#pragma unroll
        for (int i = 0; i < 8; i++) { CP16(A32o[s] + adst[i], asrc[i]); asrc[i] += BKC; }
#pragma unroll
        for (int i = 0; i < 8; i++) { CP16(Bo[s] + bdst[i], bsrc[i]); bsrc[i] += BKC; }
        CP_COMMIT();
    }

    // ---- main loop ----
    int bs = 2;                                  // B ring slot for chunk c+2
    for (int c = 0; c < NKC; c++) {
        CP_WAIT1();
        __syncthreads();
        int ab = c & 1;

        // convert A32[ab] -> A16[ab] (swizzled fp16)
        {
            uint32_t out[16];
            if (vpad) {
#pragma unroll
                for (int j = 0; j < 16; j++) out[j] = 0u;
            } else {
                const float4* sp = (const float4*)(smem + (A32o[ab] - sb) + vsrc);
#pragma unroll
                for (int j = 0; j < 8; j++) {
                    float4 f = sp[j];
                    __half2 h0 = __floats2half2_rn(f.x, f.y);
                    __half2 h1 = __floats2half2_rn(f.z, f.w);
                    out[2 * j]     = *(uint32_t*)&h0;
                    out[2 * j + 1] = *(uint32_t*)&h1;
                }
            }
#pragma unroll
            for (int q = 0; q < 4; q++)
                *(uint4*)(smem + (A16o[ab] - sb) + vdst[q]) =
                    make_uint4(out[4 * q], out[4 * q + 1], out[4 * q + 2], out[4 * q + 3]);
        }
        __syncthreads();

        // issue chunk c+2: A into A32[ab] (just drained), B into ring slot bs
        if (c + 2 < NKC) {
#pragma unroll
            for (int i = 0; i < 8; i++) { CP16(A32o[ab] + adst[i], asrc[i]); asrc[i] += BKC; }
#pragma unroll
            for (int i = 0; i < 8; i++) { CP16(Bo[bs] + bdst[i], bsrc[i]); bsrc[i] += BKC; }
        }
        CP_COMMIT();
        bs = (bs == 2) ? 0 : bs + 1;

        uint32_t stA = A16o[ab];
        uint32_t stB = Bo[c % 3];

#pragma unroll
        for (int kk = 0; kk < 4; kk++) {
            uint32_t ko = (uint32_t)(kk * 32 + hh * 16);
            uint32_t ah[4][4], bh[8][2];
#pragma unroll
            for (int mt = 0; mt < 4; mt++) {
                uint32_t ad = stA + cA[mt] + (ko ^ swA[mt]);
                LDSM4(ah[mt][0], ah[mt][1], ah[mt][2], ah[mt][3], ad);
            }
#pragma unroll
            for (int q = 0; q < 4; q++) {
                uint32_t ad = stB + cB[q] + (ko ^ swB[q]);
                uint32_t r0, r1, r2, r3;
                LDSM4(r0, r1, r2, r3, ad);
                bh[2 * q][0] = r0; bh[2 * q + 1][0] = r1;
                bh[2 * q][1] = r2; bh[2 * q + 1][1] = r3;
            }
#pragma unroll
            for (int mt = 0; mt < 4; mt++)
#pragma unroll
                for (int nt = 0; nt < 8; nt++)
                    MMA16816(acc[mt][nt], ah[mt], bh[nt]);
        }
    }

    // ---- epilogue: bias + GLU -> d_U ----
    // branch == bn (BN=256 covers one branch); col(2t)="a", col(2t+1)="gate"
    int g = lane >> 2, t = lane & 3;
    const float* bias = bn ? mcb : ccb;
    int ucb = bn << 7;
#pragma unroll
    for (int mt = 0; mt < 4; mt++) {
        int r0 = m0 + wm * 64 + mt * 16 + g;
#pragma unroll
        for (int nt = 0; nt < 8; nt++) {
            int p = wn * 32 + nt * 4 + t;         // GLU pair within branch
            float ba = __ldg(bias + p);
            float bg = __ldg(bias + 128 + p);
            int uc = ucb + p;
            float a0 = acc[mt][nt][0] + ba;
            float g0 = acc[mt][nt][1] + bg;
            d_U[(size_t)r0 * 256 + uc] = a0 / (1.f + __expf(-g0));
            float a1 = acc[mt][nt][2] + ba;
            float g1 = acc[mt][nt][3] + bg;
            d_U[(size_t)(r0 + 8) * 256 + uc] = a1 / (1.f + __expf(-g1));
        }
    }
}

// ============================================================
// K2a: ctx share + leaky + per-chunk channel max -> d_gpart.
// ============================================================
__global__ __launch_bounds__(256) void share_ctx(const float* __restrict__ csb) {
    __shared__ float u[32][132];
    __shared__ float redmax[8][CC];
    int tid = threadIdx.x;
    int blk = blockIdx.x;
    int b = blk / GCHUNKS, ch = blk % GCHUNKS;
    int row0 = b * TOUT + ch * 31;

    for (int i = tid; i < 32 * 32; i += 256) {
        int r = i >> 5, q4 = (i & 31) * 4;
        float4 v = *(const float4*)(d_U + (size_t)(row0 + r) * 256 + q4);
        u[r][q4] = v.x; u[r][q4 + 1] = v.y; u[r][q4 + 2] = v.z; u[r][q4 + 3] = v.w;
    }
    __syncthreads();

    int ty = tid >> 5;
    int tx = tid & 31;
    int ol = tx * 4;
    const float* wt = d_WsT[0];

    float acc[4][4];
#pragma unroll
    for (int i = 0; i < 4; i++)
#pragma unroll
        for (int j = 0; j < 4; j++) acc[i][j] = 0.f;

    for (int c = 0; c < CC; c++) {
        float4 w0 = __ldg((const float4*)(wt + c * CC + ol));
        float wv[4] = {w0.x, w0.y, w0.z, w0.w};
        float uv[4];
#pragma unroll
        for (int i = 0; i < 4; i++) uv[i] = u[ty * 4 + i][c];
#pragma unroll
        for (int i = 0; i < 4; i++)
#pragma unroll
            for (int j = 0; j < 4; j++) acc[i][j] += uv[i] * wv[j];
    }

    float b4[4];
#pragma unroll
    for (int j = 0; j < 4; j++) b4[j] = __ldg(csb + ol + j);

    float m4[4] = {-INFINITY, -INFINITY, -INFINITY, -INFINITY};
#pragma unroll
    for (int i = 0; i < 4; i++) {
        int lr = ty * 4 + i;
        if (lr < 31) {
#pragma unroll
            for (int j = 0; j < 4; j++) {
                float v = acc[i][j] + b4[j];
                v = (v >= 0.f) ? v : 0.01f * v;
                m4[j] = fmaxf(m4[j], v);
            }
        }
    }
#pragma unroll
    for (int j = 0; j < 4; j++) redmax[ty][ol + j] = m4[j];
    __syncthreads();
    if (tid < CC) {
        float m = redmax[0][tid];
#pragma unroll
        for (int i = 1; i < 8; i++) m = fmaxf(m, redmax[i][tid]);
        d_gpart[(size_t)blk * CC + tid] = m;
    }
}

// K3: fused gct reduce + q projection.
__global__ void gct_q(const float* __restrict__ w, const float* __restrict__ bq) {
    __shared__ float gs[CC];
    int b = blockIdx.x, c = threadIdx.x;
    float m = -INFINITY;
    for (int i = 0; i < GCHUNKS; i++)
        m = fmaxf(m, d_gpart[((size_t)b * GCHUNKS + i) * CC + c]);
    gs[c] = m;
    __syncthreads();
    float s = __ldg(bq + c);
    const float* wp = w + c * CC;
#pragma unroll 4
    for (int k = 0; k < CC; k++) s += gs[k] * __ldg(wp + k);
    d_q[b * CC + c] = tanhf(s);
}

// ============================================================
// K2b: main share + leaky (SMEM) + fused gate + per-chunk max.
// ============================================================
__global__ __launch_bounds__(256) void share_main_gate(const float* __restrict__ msb) {
    __shared__ float u[32][132];
    __shared__ float hs[32][CC];
    __shared__ float qs[CC];
    __shared__ float wm[8][CC];
    int tid = threadIdx.x;
    int blk = blockIdx.x;
    int b = blk / GCHUNKS, ch = blk % GCHUNKS;
    int row0 = b * TOUT + ch * 31;

    if (tid < CC) qs[tid] = d_q[b * CC + tid];
    for (int i = tid; i < 32 * 32; i += 256) {
        int r = i >> 5, q4 = (i & 31) * 4;
        float4 v = *(const float4*)(d_U + (size_t)(row0 + r) * 256 + 128 + q4);
        u[r][q4] = v.x; u[r][q4 + 1] = v.y; u[r][q4 + 2] = v.z; u[r][q4 + 3] = v.w;
    }
    __syncthreads();

    int ty = tid >> 5;
    int tx = tid & 31;
    int ol = tx * 4;
    const float* wt = d_WsT[1];

    float acc[4][4];
#pragma unroll
    for (int i = 0; i < 4; i++)
#pragma unroll
        for (int j = 0; j < 4; j++) acc[i][j] = 0.f;

    for (int c = 0; c < CC; c++) {
        float4 w0 = __ldg((const float4*)(wt + c * CC + ol));
        float wv[4] = {w0.x, w0.y, w0.z, w0.w};
        float uv[4];
#pragma unroll
        for (int i = 0; i < 4; i++) uv[i] = u[ty * 4 + i][c];
#pragma unroll
        for (int i = 0; i < 4; i++)
#pragma unroll
            for (int j = 0; j < 4; j++) acc[i][j] += uv[i] * wv[j];
    }

    float b4[4];
#pragma unroll
    for (int j = 0; j < 4; j++) b4[j] = __ldg(msb + ol + j);
#pragma unroll
    for (int i = 0; i < 4; i++) {
        int lr = ty * 4 + i;
#pragma unroll
        for (int j = 0; j < 4; j++) {
            float v = acc[i][j] + b4[j];
            hs[lr][ol + j] = (v >= 0.f) ? v : 0.01f * v;
        }
    }
    __syncthreads();

    int w = tid >> 5, lane = tid & 31;
    float vmax[4] = {-INFINITY, -INFINITY, -INFINITY, -INFINITY};
#pragma unroll
    for (int rep = 0; rep < 4; rep++) {
        int lr = rep * 8 + w;
        if (lr < 31) {
            float hv[4];
            float dot = 0.f;
#pragma unroll
            for (int j = 0; j < 4; j++) {
                hv[j] = hs[lr][lane + 32 * j];
                dot += hv[j] * qs[lane + 32 * j];
            }
#pragma unroll
            for (int off = 16; off; off >>= 1)
                dot += __shfl_xor_sync(0xffffffff, dot, off);
            float gate = 1.f / (1.f + __expf(-dot));
#pragma unroll
            for (int j = 0; j < 4; j++)
                vmax[j] = fmaxf(vmax[j], hv[j] * gate);
        }
    }
#pragma unroll
    for (int j = 0; j < 4; j++) wm[w][lane + 32 * j] = vmax[j];
    __syncthreads();
    if (tid < CC) {
        float m = wm[0][tid];
#pragma unroll
        for (int i = 1; i < 8; i++) m = fmaxf(m, wm[i][tid]);
        d_part[(size_t)blk * CC + tid] = m;
    }
}

// K6: final reduce -> out (B, C)
__global__ void final_max(float* __restrict__ out) {
    int b = blockIdx.x, c = threadIdx.x;
    float m = -INFINITY;
    for (int i = 0; i < GCHUNKS; i++)
        m = fmaxf(m, d_part[((size_t)b * GCHUNKS + i) * CC + c]);
    out[b * CC + c] = m;
}

// ============================================================
extern "C" void kernel_launch(void* const* d_in, const int* in_sizes, int n_in,
                              void* d_out, int out_size) {
    const float* x   = (const float*)d_in[0];
    const float* ccw = (const float*)d_in[1];
    const float* ccb = (const float*)d_in[2];
    const float* csw = (const float*)d_in[3];
    const float* csb = (const float*)d_in[4];
    const float* mcw = (const float*)d_in[5];
    const float* mcb = (const float*)d_in[6];
    const float* msw = (const float*)d_in[7];
    const float* msb = (const float*)d_in[8];
    const float* gpw = (const float*)d_in[9];
    const float* gpb = (const float*)d_in[10];
    float* out = (float*)d_out;

    static int smem_set = 0;
    if (!smem_set) {
        cudaFuncSetAttribute(gemm_tc, cudaFuncAttributeMaxDynamicSharedMemorySize, SMEM_DYN);
        smem_set = 1;
    }

    prep_w<<<8192 + 64, 256>>>(ccw, mcw, csw, msw);

    gemm_tc<<<dim3(2, MP / BM), 256, SMEM_DYN>>>(ccb, mcb, x);

    share_ctx<<<BB * GCHUNKS, 256>>>(csb);
    gct_q<<<BB, CC>>>(gpw, gpb);
    share_main_gate<<<BB * GCHUNKS, 256>>>(msb);
    final_max<<<BB, CC>>>(out);
}